// round 13
// baseline (speedup 1.0000x reference)
#include <cuda_runtime.h>
#include <math.h>
#include <stdint.h>

#define N_NODES 12800
#define N_EDGES 204800
#define DIM 16

typedef unsigned long long ull;

// ---------------- scratch (static device memory, no allocs) ----------------
__device__ float g_out0[N_NODES * DIM];     // node state ping-pong
__device__ float g_out1[N_NODES * DIM];
__device__ float g_hd[N_EDGES * DIM];       // edge hidden, dst-rank-sorted order
__device__ int   g_srcs[N_EDGES];           // src node id per dst-sorted slot
__device__ int   g_dst_cnt[N_NODES];        // zero at load; re-zeroed by k_scan
__device__ int   g_nid[N_NODES];            // rank -> node id (in-degree sorted)
__device__ int   g_roff[N_NODES + 1];       // rank -> edge offset
__device__ int   g_cur[N_NODES];            // node -> scatter cursor
__device__ float g_invdeg[N_NODES];

// ---------------- setup ----------------
// blocks [0,800): dst histogram; blocks [800,1600): lin0 -> g_out0.
__global__ void k_hist(const float* __restrict__ x, const int* __restrict__ ei,
                       const float* __restrict__ l0w, const float* __restrict__ l0b) {
    int gb = blockIdx.x;
    if (gb < N_EDGES / 256) {
        int e = gb * 256 + threadIdx.x;
        atomicAdd(&g_dst_cnt[ei[N_EDGES + e]], 1);
    } else {
        int i = (gb - N_EDGES / 256) * 256 + threadIdx.x;
        int n = i >> 4, k = i & 15;
        float acc = l0b[k];
#pragma unroll
        for (int c = 0; c < 3; ++c) acc += x[n * 3 + c] * l0w[k * 3 + c];
        g_out0[i] = fmaxf(acc, 0.0f);
    }
}

// Single block: counting-sort nodes by IN-degree -> g_nid/g_roff/g_cur,
// invdeg; re-zeroes dst counts for the next kernel_launch call.
__global__ void k_scan() {
    int tid = threadIdx.x, lane = tid & 31, wid = tid >> 5;
    __shared__ int hist[1024];
    __shared__ int nbase[1024];
    __shared__ int ebase[1024];
    __shared__ int wc[32], we[32];
    hist[tid] = 0;
    __syncthreads();
    for (int n = tid; n < N_NODES; n += 1024) {
        int d = g_dst_cnt[n]; if (d > 1023) d = 1023;
        atomicAdd(&hist[d], 1);
    }
    __syncthreads();
    int c = hist[tid];
    int ec = c * tid;                    // edge count contributed by this bin
    int ci = c, ei2 = ec;
#pragma unroll
    for (int s = 1; s < 32; s <<= 1) {
        int v = __shfl_up_sync(0xffffffffu, ci, s);
        int w2 = __shfl_up_sync(0xffffffffu, ei2, s);
        if (lane >= s) { ci += v; ei2 += w2; }
    }
    if (lane == 31) { wc[wid] = ci; we[wid] = ei2; }
    __syncthreads();
    if (wid == 0) {
        int v = wc[lane], iv = v, e = we[lane], ie = e;
#pragma unroll
        for (int s = 1; s < 32; s <<= 1) {
            int t1 = __shfl_up_sync(0xffffffffu, iv, s);
            int t2 = __shfl_up_sync(0xffffffffu, ie, s);
            if (lane >= s) { iv += t1; ie += t2; }
        }
        wc[lane] = iv - v; we[lane] = ie - e;
    }
    __syncthreads();
    nbase[tid] = wc[wid] + (ci - c);
    ebase[tid] = we[wid] + (ei2 - ec);
    hist[tid] = 0;                       // reuse as intra-bin cursor
    __syncthreads();
    for (int n = tid; n < N_NODES; n += 1024) {
        int d = g_dst_cnt[n]; if (d > 1023) d = 1023;
        g_dst_cnt[n] = 0;                // re-zero for next call
        int t = atomicAdd(&hist[d], 1);
        int rank = nbase[d] + t;
        int eoff = ebase[d] + t * d;
        g_nid[rank] = n;
        g_roff[rank] = eoff;
        g_cur[n] = eoff;
        g_invdeg[n] = 1.0f / fmaxf((float)d, 1.0f);
    }
    if (tid == 0) g_roff[N_NODES] = N_EDGES;
}

// Per edge: place into dst-rank-sorted slot p, record src id, compute edge
// hidden h = relu(ea @ nn1_w^T + nn1_b) directly into g_hd[p].
__global__ void k_scatter(const int* __restrict__ ei, const float* __restrict__ ea,
                          const float* __restrict__ n1w, const float* __restrict__ n1b) {
    int e = blockIdx.x * blockDim.x + threadIdx.x;
    if (e >= N_EDGES) return;
    int d = ei[N_EDGES + e];
    int p = atomicAdd(&g_cur[d], 1);
    g_srcs[p] = ei[e];
    float4 a = __ldg((const float4*)&ea[e * 4]);
    float* hd = &g_hd[p * DIM];
#pragma unroll
    for (int j = 0; j < 16; j += 4) {
        float4 h;
        h.x = fmaxf(n1b[j + 0] + a.x * n1w[(j + 0) * 4] + a.y * n1w[(j + 0) * 4 + 1] +
                    a.z * n1w[(j + 0) * 4 + 2] + a.w * n1w[(j + 0) * 4 + 3], 0.0f);
        h.y = fmaxf(n1b[j + 1] + a.x * n1w[(j + 1) * 4] + a.y * n1w[(j + 1) * 4 + 1] +
                    a.z * n1w[(j + 1) * 4 + 2] + a.w * n1w[(j + 1) * 4 + 3], 0.0f);
        h.z = fmaxf(n1b[j + 2] + a.x * n1w[(j + 2) * 4] + a.y * n1w[(j + 2) * 4 + 1] +
                    a.z * n1w[(j + 2) * 4 + 2] + a.w * n1w[(j + 2) * 4 + 3], 0.0f);
        h.w = fmaxf(n1b[j + 3] + a.x * n1w[(j + 3) * 4] + a.y * n1w[(j + 3) * 4 + 1] +
                    a.z * n1w[(j + 3) * 4 + 2] + a.w * n1w[(j + 3) * 4 + 3], 0.0f);
        *(float4*)&hd[j] = h;
    }
}

// ---------------- fused per-round kernel (G-factorization) ----------------
// 512 threads = 16 warps = 16 dst-ranks (consecutive -> equal in-degree).
// Mainloop: lane owns (d = lane>>1, j-half = lane&1); per edge accumulate
// G[d][j] += out[src,d]*h[e,j] (4 FMA2) and G1[d] += out[src,d], in regs.
// Epilogue: dump G to smem; lane (k = lane&15, half = lane>>4) contracts
// aggr[k] = sum_{d,j} G[d][j]*W2[d*16+k, j] + sum_d G1[d]*b2[d*16+k]
// (half-split over d, shfl_xor(16) combine). Then fused mean + root + ReLU +
// GRU; write new state to outw (d_out on the last round). No message buffer.
__global__ void __launch_bounds__(512) k_round(
    const float* __restrict__ w2, const float* __restrict__ b2,
    const float* __restrict__ cr, const float* __restrict__ cb,
    const float* __restrict__ wih, const float* __restrict__ whh,
    const float* __restrict__ bih, const float* __restrict__ bhh,
    const float* __restrict__ outr, float* __restrict__ outw) {
    __shared__ ull s_w2p[2048];              // [d][jj][k], j-pairs: 16 KB
    __shared__ __align__(16) ull s_G[16][16][8];  // per warp [d][jj]: 16 KB
    __shared__ float s_G1[16][16];
    __shared__ float s_b2[256];              // [d][k]
    __shared__ float s_cr[256];              // [d][k]
    __shared__ float s_wih[768];             // transposed [d][gate]
    __shared__ float s_whh[768];
    __shared__ float s_out[16][16];
    __shared__ float s_m[16][16];

    int tid = threadIdx.x, lane = tid & 31, w = tid >> 5;
    int rank = blockIdx.x * 16 + w;
    int n = g_nid[rank];

    for (int i = tid; i < 4096; i += 512) {
        int d = i >> 8, kk = (i >> 4) & 15, j = i & 15;
        ((float*)&s_w2p[(d * 8 + (j >> 1)) * 16 + kk])[j & 1] = w2[i];
    }
    if (tid < 256) { s_b2[tid] = b2[tid]; s_cr[tid] = cr[tid]; }
    for (int i = tid; i < 768; i += 512) {
        int rr = i >> 4, d = i & 15;
        s_wih[d * 48 + rr] = wih[i];
        s_whh[d * 48 + rr] = whh[i];
    }
    if (tid < 256) {
        int node = g_nid[blockIdx.x * 16 + (tid >> 4)];
        s_out[tid >> 4][tid & 15] = outr[node * 16 + (tid & 15)];
    }
    __syncthreads();

    // ---- mainloop: accumulate G (rank-1 updates) in registers ----
    int d_l = lane >> 1, jh = lane & 1;
    ull G0 = 0, G1r = 0, G2 = 0, G3 = 0;
    float Gb = 0.0f;
    int beg = g_roff[rank], end = g_roff[rank + 1];
    const ulonglong2* hp = (const ulonglong2*)g_hd;
    if (beg < end) {
        int src = __ldg(&g_srcs[beg]);
        float od = __ldg(&outr[src * 16 + d_l]);
        for (int i = beg; i < end; ++i) {
            int ip = i + 1 < end ? i + 1 : i;      // branch-free prefetch
            int srcn = __ldg(&g_srcs[ip]);
            float odn = __ldg(&outr[srcn * 16 + d_l]);
            ulonglong2 X = __ldg(&hp[i * 4 + jh * 2]);
            ulonglong2 Y = __ldg(&hp[i * 4 + jh * 2 + 1]);
            ull od2;
            asm("mov.b64 %0,{%1,%1};" : "=l"(od2) : "f"(od));
            asm("fma.rn.f32x2 %0,%1,%2,%0;" : "+l"(G0) : "l"(od2), "l"(X.x));
            asm("fma.rn.f32x2 %0,%1,%2,%0;" : "+l"(G1r) : "l"(od2), "l"(X.y));
            asm("fma.rn.f32x2 %0,%1,%2,%0;" : "+l"(G2) : "l"(od2), "l"(Y.x));
            asm("fma.rn.f32x2 %0,%1,%2,%0;" : "+l"(G3) : "l"(od2), "l"(Y.y));
            Gb += od;
            od = odn;
        }
    }
    // dump G to smem ([d][jj] with jj global = jh*4 + 0..3)
    ulonglong2* gg = (ulonglong2*)&s_G[w][d_l][jh * 4];
    gg[0] = make_ulonglong2(G0, G1r);
    gg[1] = make_ulonglong2(G2, G3);
    if (jh == 0) s_G1[w][d_l] = Gb;
    __syncwarp();

    // ---- contraction: aggr[k] = sum G*W2 (+ G1*b2), half-split over d ----
    int k = lane & 15, h2 = lane >> 4;
    ull acc = 0;
    float bacc = 0.0f;
#pragma unroll
    for (int dd = 0; dd < 8; ++dd) {
        int d = h2 * 8 + dd;
        bacc += s_G1[w][d] * s_b2[d * 16 + k];
#pragma unroll
        for (int jj = 0; jj < 8; ++jj) {
            ull gv = s_G[w][d][jj];
            ull wv = s_w2p[(d * 8 + jj) * 16 + k];
            asm("fma.rn.f32x2 %0,%1,%2,%0;" : "+l"(acc) : "l"(gv), "l"(wv));
        }
    }
    float lo, hi;
    asm("mov.b64 {%0,%1},%2;" : "=f"(lo), "=f"(hi) : "l"(acc));
    float t = lo + hi + bacc;
    t += __shfl_xor_sync(0xffffffffu, t, 16);      // combine d-halves

    // ---- fused update: mean + root matmul + ReLU + GRU ----
    float hprev = s_out[w][k];
    float accu = t * g_invdeg[n] + cb[k];
#pragma unroll
    for (int d = 0; d < 16; ++d) accu += s_out[w][d] * s_cr[d * 16 + k];
    float m = fmaxf(accu, 0.0f);
    if (h2 == 0) s_m[w][k] = m;
    __syncwarp();

    float gr = bih[k], gz = bih[k + 16], gn = bih[k + 32];
    float hr = bhh[k], hz = bhh[k + 16], hn = bhh[k + 32];
#pragma unroll
    for (int d = 0; d < 16; ++d) {
        float md = s_m[w][d], hd = s_out[w][d];
        gr += md * s_wih[d * 48 + k];
        gz += md * s_wih[d * 48 + k + 16];
        gn += md * s_wih[d * 48 + k + 32];
        hr += hd * s_whh[d * 48 + k];
        hz += hd * s_whh[d * 48 + k + 16];
        hn += hd * s_whh[d * 48 + k + 32];
    }
    float rr = 1.0f / (1.0f + expf(-(gr + hr)));
    float zz = 1.0f / (1.0f + expf(-(gz + hz)));
    float nh = tanhf(gn + rr * hn);
    if (h2 == 0) outw[n * 16 + k] = (1.0f - zz) * nh + zz * hprev;
}

// ---------------- host launcher ----------------
extern "C" void kernel_launch(void* const* d_in, const int* in_sizes, int n_in,
                              void* d_out, int out_size) {
    const float* x         = (const float*)d_in[0];
    const int*   ei        = (const int*)  d_in[1];
    const float* ea        = (const float*)d_in[2];
    const float* lin0_w    = (const float*)d_in[3];
    const float* lin0_b    = (const float*)d_in[4];
    const float* nn1_w     = (const float*)d_in[5];
    const float* nn1_b     = (const float*)d_in[6];
    const float* nn2_w     = (const float*)d_in[7];
    const float* nn2_b     = (const float*)d_in[8];
    const float* conv_root = (const float*)d_in[9];
    const float* conv_bias = (const float*)d_in[10];
    const float* w_ih      = (const float*)d_in[11];
    const float* w_hh      = (const float*)d_in[12];
    const float* b_ih      = (const float*)d_in[13];
    const float* b_hh      = (const float*)d_in[14];

    float *o0 = nullptr, *o1 = nullptr;
    cudaGetSymbolAddress((void**)&o0, g_out0);
    cudaGetSymbolAddress((void**)&o1, g_out1);

    k_hist<<<N_EDGES / 256 + (N_NODES * DIM) / 256, 256>>>(x, ei, lin0_w, lin0_b);
    k_scan<<<1, 1024>>>();
    k_scatter<<<(N_EDGES + 255) / 256, 256>>>(ei, ea, nn1_w, nn1_b);

    // r=0 reads o0 (lin0), writes o1; alternate; r=5 reads o1, writes d_out.
    for (int r = 0; r < 6; ++r) {
        const float* orr = (r & 1) ? o1 : o0;
        float* ow = (r == 5) ? (float*)d_out : ((r & 1) ? o0 : o1);
        k_round<<<N_NODES / 16, 512>>>(nn2_w, nn2_b, conv_root, conv_bias,
                                       w_ih, w_hh, b_ih, b_hh, orr, ow);
    }
}

// round 14
// speedup vs baseline: 1.0973x; 1.0973x over previous
#include <cuda_runtime.h>
#include <math.h>
#include <stdint.h>

#define N_NODES 12800
#define N_EDGES 204800
#define DIM 16
#define NBLK 400   // k_msg grid; rank stride for interleaved assignment

typedef unsigned long long ull;

// ---------------- scratch (static device memory, no allocs) ----------------
__device__ float g_out[N_NODES * DIM];
__device__ float g_hs[N_EDGES * DIM];       // edge hidden, rank-sorted order
__device__ int   g_qs[N_EDGES];             // rank-sorted slot -> dst-sorted slot
__device__ float g_msg[N_EDGES * DIM];      // messages (dst-sorted)
__device__ int   g_src_cnt[N_NODES];        // zero at load; re-zeroed by k_scan
__device__ int   g_dst_cnt[N_NODES];        // zero at load; re-zeroed by k_scan
__device__ int   g_nid[N_NODES];            // rank -> node id (out-degree sorted)
__device__ int   g_roff[N_NODES + 1];       // rank -> edge offset
__device__ int   g_dst_off[N_NODES + 1];    // node -> incoming msg offset
__device__ int   g_src_cur[N_NODES];
__device__ int   g_dst_cur[N_NODES];
__device__ float g_invdeg[N_NODES];

// ---------------- setup ----------------
// blocks [0,800): edge histograms; blocks [800,1600): lin0.
__global__ void k_hist(const float* __restrict__ x, const int* __restrict__ ei,
                       const float* __restrict__ l0w, const float* __restrict__ l0b) {
    int gb = blockIdx.x;
    if (gb < N_EDGES / 256) {
        int e = gb * 256 + threadIdx.x;
        atomicAdd(&g_src_cnt[ei[e]], 1);
        atomicAdd(&g_dst_cnt[ei[N_EDGES + e]], 1);
    } else {
        int i = (gb - N_EDGES / 256) * 256 + threadIdx.x;
        int n = i >> 4, k = i & 15;
        float acc = l0b[k];
#pragma unroll
        for (int c = 0; c < 3; ++c) acc += x[n * 3 + c] * l0w[k * 3 + c];
        g_out[i] = fmaxf(acc, 0.0f);
    }
}

// block 0: counting-sort nodes by out-degree -> g_nid/g_roff/g_src_cur.
// block 1: exclusive scan of dst counts -> g_dst_off/g_dst_cur + invdeg.
// Both re-zero their count arrays for the next kernel_launch call.
__global__ void k_scan() {
    int tid = threadIdx.x, lane = tid & 31, wid = tid >> 5;
    if (blockIdx.x == 1) {
        const int PER = 13;
        int base = tid * PER;
        int c[PER];
        int local = 0;
#pragma unroll
        for (int i = 0; i < PER; ++i) {
            int idx = base + i;
            c[i] = (idx < N_NODES) ? g_dst_cnt[idx] : 0;
            local += c[i];
        }
        int incl = local;
#pragma unroll
        for (int s = 1; s < 32; s <<= 1) {
            int v = __shfl_up_sync(0xffffffffu, incl, s);
            if (lane >= s) incl += v;
        }
        __shared__ int wsum[32];
        if (lane == 31) wsum[wid] = incl;
        __syncthreads();
        if (wid == 0) {
            int v = wsum[lane], iv = v;
#pragma unroll
            for (int s = 1; s < 32; s <<= 1) {
                int t = __shfl_up_sync(0xffffffffu, iv, s);
                if (lane >= s) iv += t;
            }
            wsum[lane] = iv - v;
        }
        __syncthreads();
        int run = wsum[wid] + (incl - local);
#pragma unroll
        for (int i = 0; i < PER; ++i) {
            int idx = base + i;
            if (idx < N_NODES) {
                g_dst_off[idx] = run;
                g_dst_cur[idx] = run;
                g_invdeg[idx] = 1.0f / fmaxf((float)c[i], 1.0f);
                g_dst_cnt[idx] = 0;
                run += c[i];
            }
        }
        if (tid == 1023) g_dst_off[N_NODES] = run;
        return;
    }
    // ---- block 0: counting sort by out-degree ----
    __shared__ int hist[1024];
    __shared__ int nbase[1024];
    __shared__ int ebase[1024];
    __shared__ int wc[32], we[32];
    hist[tid] = 0;
    __syncthreads();
    for (int n = tid; n < N_NODES; n += 1024) {
        int d = g_src_cnt[n]; if (d > 1023) d = 1023;
        atomicAdd(&hist[d], 1);
    }
    __syncthreads();
    int c = hist[tid];
    int ec = c * tid;
    int ci = c, ei2 = ec;
#pragma unroll
    for (int s = 1; s < 32; s <<= 1) {
        int v = __shfl_up_sync(0xffffffffu, ci, s);
        int w2 = __shfl_up_sync(0xffffffffu, ei2, s);
        if (lane >= s) { ci += v; ei2 += w2; }
    }
    if (lane == 31) { wc[wid] = ci; we[wid] = ei2; }
    __syncthreads();
    if (wid == 0) {
        int v = wc[lane], iv = v, e = we[lane], ie = e;
#pragma unroll
        for (int s = 1; s < 32; s <<= 1) {
            int t1 = __shfl_up_sync(0xffffffffu, iv, s);
            int t2 = __shfl_up_sync(0xffffffffu, ie, s);
            if (lane >= s) { iv += t1; ie += t2; }
        }
        wc[lane] = iv - v; we[lane] = ie - e;
    }
    __syncthreads();
    nbase[tid] = wc[wid] + (ci - c);
    ebase[tid] = we[wid] + (ei2 - ec);
    hist[tid] = 0;                 // reuse as intra-bin cursor
    __syncthreads();
    for (int n = tid; n < N_NODES; n += 1024) {
        int d = g_src_cnt[n]; if (d > 1023) d = 1023;
        g_src_cnt[n] = 0;
        int t = atomicAdd(&hist[d], 1);
        int rank = nbase[d] + t;
        int eoff = ebase[d] + t * d;
        g_nid[rank] = n;
        g_roff[rank] = eoff;
        g_src_cur[n] = eoff;
    }
    if (tid == 0) g_roff[N_NODES] = N_EDGES;
}

// Per edge: place into rank-sorted slot p, record its dst-sorted slot q,
// compute edge hidden h = relu(ea @ nn1_w^T + nn1_b) directly into g_hs[p].
__global__ void k_scatter(const int* __restrict__ ei, const float* __restrict__ ea,
                          const float* __restrict__ n1w, const float* __restrict__ n1b) {
    int e = blockIdx.x * blockDim.x + threadIdx.x;
    if (e >= N_EDGES) return;
    int s = ei[e], d = ei[N_EDGES + e];
    int p = atomicAdd(&g_src_cur[s], 1);
    int q = atomicAdd(&g_dst_cur[d], 1);
    g_qs[p] = q;
    float4 a = __ldg((const float4*)&ea[e * 4]);
    float* hd = &g_hs[p * DIM];
#pragma unroll
    for (int j = 0; j < 16; j += 4) {
        float4 h;
        h.x = fmaxf(n1b[j + 0] + a.x * n1w[(j + 0) * 4] + a.y * n1w[(j + 0) * 4 + 1] +
                    a.z * n1w[(j + 0) * 4 + 2] + a.w * n1w[(j + 0) * 4 + 3], 0.0f);
        h.y = fmaxf(n1b[j + 1] + a.x * n1w[(j + 1) * 4] + a.y * n1w[(j + 1) * 4 + 1] +
                    a.z * n1w[(j + 1) * 4 + 2] + a.w * n1w[(j + 1) * 4 + 3], 0.0f);
        h.z = fmaxf(n1b[j + 2] + a.x * n1w[(j + 2) * 4] + a.y * n1w[(j + 2) * 4 + 1] +
                    a.z * n1w[(j + 2) * 4 + 2] + a.w * n1w[(j + 2) * 4 + 3], 0.0f);
        h.w = fmaxf(n1b[j + 3] + a.x * n1w[(j + 3) * 4] + a.y * n1w[(j + 3) * 4 + 1] +
                    a.z * n1w[(j + 3) * 4 + 2] + a.w * n1w[(j + 3) * 4 + 3], 0.0f);
        *(float4*)&hd[j] = h;
    }
}

// ---------------- per-round kernels ----------------
// k_msg: 128 threads = 32 ranks x 4 lanes. Rank assignment is INTERLEAVED:
// group g of block b handles rank g*NBLK + b. Consequences:
//  - every block holds one node from each degree-slice of 400 -> equal
//    block work (single-wave grid stays balanced across SMs);
//  - a warp's 8 groups span a narrow degree band -> max~mean loop bounds.
__global__ void __launch_bounds__(128) k_msg(const float* __restrict__ w2,
                                             const float* __restrict__ b2) {
    __shared__ ull s_w2p[16 * 8 * 16];   // [d][jj][k], j-pairs packed, 16KB
    __shared__ float s_b2[256];          // [d][k]
    __shared__ float s_out[32][17];
    int tid = threadIdx.x;
    for (int i = tid; i < 4096; i += 128) {
        int d = i >> 8, k = (i >> 4) & 15, j = i & 15;
        ((float*)&s_w2p[(d * 8 + (j >> 1)) * 16 + k])[j & 1] = w2[i];
    }
    for (int i = tid; i < 256; i += 128) s_b2[i] = b2[i];
    int bx = blockIdx.x;
    for (int i = tid; i < 32 * DIM; i += 128) {
        int node = g_nid[(i >> 4) * NBLK + bx];       // interleaved rank
        s_out[i >> 4][i & 15] = g_out[node * DIM + (i & 15)];
    }
    __syncthreads();

    int l = tid & 3;                     // k-quad index
    int g = tid >> 2;                    // group within block
    int rank = g * NBLK + bx;            // interleaved rank

    ull p2[32];                          // [kk][jj]
    float xb[4];
#pragma unroll
    for (int i = 0; i < 32; ++i) p2[i] = 0ull;
#pragma unroll
    for (int kk = 0; kk < 4; ++kk) xb[kk] = 0.0f;
#pragma unroll
    for (int d = 0; d < 16; ++d) {
        float od = s_out[g][d];
        ull od2;
        asm("mov.b64 %0,{%1,%1};" : "=l"(od2) : "f"(od));
#pragma unroll
        for (int kk = 0; kk < 4; ++kk) {
            int k = l * 4 + kk;
            xb[kk] += od * s_b2[d * 16 + k];
#pragma unroll
            for (int jj = 0; jj < 8; ++jj) {
                ull w = s_w2p[(d * 8 + jj) * 16 + k];
                asm("fma.rn.f32x2 %0,%1,%2,%0;" : "+l"(p2[kk * 8 + jj]) : "l"(od2), "l"(w));
            }
        }
    }

    int beg = g_roff[rank], end = g_roff[rank + 1];
    const ulonglong2* hsp = (const ulonglong2*)g_hs;
    for (int i = beg; i < end; ++i) {
        int q = __ldg(&g_qs[i]);
        ulonglong2 A = hsp[i * 4 + 0], B = hsp[i * 4 + 1];
        ulonglong2 C = hsp[i * 4 + 2], D = hsp[i * 4 + 3];
        float4 m4;
        float* mm = (float*)&m4;
#pragma unroll
        for (int kk = 0; kk < 4; ++kk) {
            ull acc;
            asm("mul.rn.f32x2 %0,%1,%2;" : "=l"(acc) : "l"(A.x), "l"(p2[kk * 8 + 0]));
            asm("fma.rn.f32x2 %0,%1,%2,%0;" : "+l"(acc) : "l"(A.y), "l"(p2[kk * 8 + 1]));
            asm("fma.rn.f32x2 %0,%1,%2,%0;" : "+l"(acc) : "l"(B.x), "l"(p2[kk * 8 + 2]));
            asm("fma.rn.f32x2 %0,%1,%2,%0;" : "+l"(acc) : "l"(B.y), "l"(p2[kk * 8 + 3]));
            asm("fma.rn.f32x2 %0,%1,%2,%0;" : "+l"(acc) : "l"(C.x), "l"(p2[kk * 8 + 4]));
            asm("fma.rn.f32x2 %0,%1,%2,%0;" : "+l"(acc) : "l"(C.y), "l"(p2[kk * 8 + 5]));
            asm("fma.rn.f32x2 %0,%1,%2,%0;" : "+l"(acc) : "l"(D.x), "l"(p2[kk * 8 + 6]));
            asm("fma.rn.f32x2 %0,%1,%2,%0;" : "+l"(acc) : "l"(D.y), "l"(p2[kk * 8 + 7]));
            float lo, hi;
            asm("mov.b64 {%0,%1},%2;" : "=f"(lo), "=f"(hi) : "l"(acc));
            mm[kk] = lo + hi + xb[kk];
        }
        ((float4*)g_msg)[q * 4 + l] = m4;   // 64B per edge
    }
}

// k_upd: contiguous message mean + root matmul + ReLU + GRU (natural order).
__global__ void k_upd(const float* __restrict__ cr, const float* __restrict__ cb,
                      const float* __restrict__ wih, const float* __restrict__ whh,
                      const float* __restrict__ bih, const float* __restrict__ bhh,
                      float* __restrict__ outw) {
    __shared__ float s_cr[DIM * DIM];
    __shared__ float s_wih[DIM * 3 * DIM];   // transposed [d][gate]
    __shared__ float s_whh[DIM * 3 * DIM];
    __shared__ float s_out[16][DIM];
    __shared__ float s_m[16][DIM];
    int tid = threadIdx.x;
    for (int i = tid; i < DIM * DIM; i += 256) s_cr[i] = cr[i];
    for (int i = tid; i < 3 * DIM * DIM; i += 256) {
        int r = i >> 4, d = i & 15;
        s_wih[d * 48 + r] = wih[i];
        s_whh[d * 48 + r] = whh[i];
    }
    int ln = tid >> 4, k = tid & 15;
    int n = blockIdx.x * 16 + ln;
    float hprev = g_out[n * DIM + k];
    s_out[ln][k] = hprev;
    __syncthreads();

    int beg = g_dst_off[n], end = g_dst_off[n + 1];
    float a0 = 0.0f, a1 = 0.0f, a2 = 0.0f, a3 = 0.0f;
    int q = beg;
    for (; q + 3 < end; q += 4) {
        a0 += __ldg(&g_msg[(q + 0) * DIM + k]);
        a1 += __ldg(&g_msg[(q + 1) * DIM + k]);
        a2 += __ldg(&g_msg[(q + 2) * DIM + k]);
        a3 += __ldg(&g_msg[(q + 3) * DIM + k]);
    }
    for (; q < end; ++q) a0 += __ldg(&g_msg[q * DIM + k]);
    float acc = ((a0 + a1) + (a2 + a3)) * g_invdeg[n] + cb[k];
#pragma unroll
    for (int d = 0; d < DIM; ++d) acc += s_out[ln][d] * s_cr[d * DIM + k];
    float m = fmaxf(acc, 0.0f);
    s_m[ln][k] = m;
    __syncthreads();

    float gr = bih[k], gz = bih[k + 16], gn = bih[k + 32];
    float hr = bhh[k], hz = bhh[k + 16], hn = bhh[k + 32];
#pragma unroll
    for (int d = 0; d < DIM; ++d) {
        float md = s_m[ln][d], hd = s_out[ln][d];
        gr += md * s_wih[d * 48 + k];
        gz += md * s_wih[d * 48 + k + 16];
        gn += md * s_wih[d * 48 + k + 32];
        hr += hd * s_whh[d * 48 + k];
        hz += hd * s_whh[d * 48 + k + 16];
        hn += hd * s_whh[d * 48 + k + 32];
    }
    float r = 1.0f / (1.0f + expf(-(gr + hr)));
    float z = 1.0f / (1.0f + expf(-(gz + hz)));
    float nh = tanhf(gn + r * hn);
    outw[n * DIM + k] = (1.0f - z) * nh + z * hprev;
}

// ---------------- host launcher ----------------
extern "C" void kernel_launch(void* const* d_in, const int* in_sizes, int n_in,
                              void* d_out, int out_size) {
    const float* x         = (const float*)d_in[0];
    const int*   ei        = (const int*)  d_in[1];
    const float* ea        = (const float*)d_in[2];
    const float* lin0_w    = (const float*)d_in[3];
    const float* lin0_b    = (const float*)d_in[4];
    const float* nn1_w     = (const float*)d_in[5];
    const float* nn1_b     = (const float*)d_in[6];
    const float* nn2_w     = (const float*)d_in[7];
    const float* nn2_b     = (const float*)d_in[8];
    const float* conv_root = (const float*)d_in[9];
    const float* conv_bias = (const float*)d_in[10];
    const float* w_ih      = (const float*)d_in[11];
    const float* w_hh      = (const float*)d_in[12];
    const float* b_ih      = (const float*)d_in[13];
    const float* b_hh      = (const float*)d_in[14];

    float* outp = nullptr;
    cudaGetSymbolAddress((void**)&outp, g_out);

    k_hist<<<N_EDGES / 256 + (N_NODES * DIM) / 256, 256>>>(x, ei, lin0_w, lin0_b);
    k_scan<<<2, 1024>>>();
    k_scatter<<<(N_EDGES + 255) / 256, 256>>>(ei, ea, nn1_w, nn1_b);

    for (int r = 0; r < 6; ++r) {
        k_msg<<<NBLK, 128>>>(nn2_w, nn2_b);
        k_upd<<<N_NODES / 16, 256>>>(conv_root, conv_bias, w_ih, w_hh, b_ih, b_hh,
                                     r == 5 ? (float*)d_out : outp);
    }
}

// round 15
// speedup vs baseline: 1.1708x; 1.0669x over previous
#include <cuda_runtime.h>
#include <math.h>
#include <stdint.h>

#define N_NODES 12800
#define N_EDGES 204800
#define DIM 16

typedef unsigned long long ull;

// ---------------- scratch (static device memory, no allocs) ----------------
__device__ float g_out[N_NODES * DIM];
__device__ float g_hs[N_EDGES * DIM];       // edge hidden, src-sorted order
__device__ int   g_qs[N_EDGES];             // src-sorted slot -> dst-sorted slot
__device__ float g_msg0[N_EDGES * DIM];     // message ping-pong (dst-sorted)
__device__ float g_msg1[N_EDGES * DIM];
__device__ int   g_src_cnt[N_NODES];        // zero at load; re-zeroed by k_scan
__device__ int   g_dst_cnt[N_NODES];        // zero at load; re-zeroed by k_scan
__device__ int   g_src_off[N_NODES + 1];
__device__ int   g_dst_off[N_NODES + 1];
__device__ int   g_src_cur[N_NODES];
__device__ int   g_dst_cur[N_NODES];
__device__ float g_invdeg[N_NODES];

// ---------------- setup ----------------
// blocks [0,800): edge histograms; blocks [800,1600): lin0.
__global__ void k_hist(const float* __restrict__ x, const int* __restrict__ ei,
                       const float* __restrict__ l0w, const float* __restrict__ l0b) {
    int gb = blockIdx.x;
    if (gb < N_EDGES / 256) {
        int e = gb * 256 + threadIdx.x;
        atomicAdd(&g_src_cnt[ei[e]], 1);
        atomicAdd(&g_dst_cnt[ei[N_EDGES + e]], 1);
    } else {
        int i = (gb - N_EDGES / 256) * 256 + threadIdx.x;
        int n = i >> 4, k = i & 15;
        float acc = l0b[k];
#pragma unroll
        for (int c = 0; c < 3; ++c) acc += x[n * 3 + c] * l0w[k * 3 + c];
        g_out[i] = fmaxf(acc, 0.0f);
    }
}

// Shuffle-based exclusive scans: block 0 = src counts, block 1 = dst (+invdeg).
// Both re-zero their count arrays for the next kernel_launch call.
__global__ void k_scan() {
    const int PER = 13;
    int which = blockIdx.x;
    int* cnt = which ? g_dst_cnt : g_src_cnt;
    int* off = which ? g_dst_off : g_src_off;
    int* cur = which ? g_dst_cur : g_src_cur;
    int tid = threadIdx.x, lane = tid & 31, wid = tid >> 5;
    int base = tid * PER;
    int c[PER];
    int local = 0;
#pragma unroll
    for (int i = 0; i < PER; ++i) {
        int idx = base + i;
        c[i] = (idx < N_NODES) ? cnt[idx] : 0;
        local += c[i];
    }
    int incl = local;
#pragma unroll
    for (int s = 1; s < 32; s <<= 1) {
        int v = __shfl_up_sync(0xffffffffu, incl, s);
        if (lane >= s) incl += v;
    }
    __shared__ int wsum[32];
    if (lane == 31) wsum[wid] = incl;
    __syncthreads();
    if (wid == 0) {
        int v = wsum[lane], iv = v;
#pragma unroll
        for (int s = 1; s < 32; s <<= 1) {
            int t = __shfl_up_sync(0xffffffffu, iv, s);
            if (lane >= s) iv += t;
        }
        wsum[lane] = iv - v;
    }
    __syncthreads();
    int run = wsum[wid] + (incl - local);
#pragma unroll
    for (int i = 0; i < PER; ++i) {
        int idx = base + i;
        if (idx < N_NODES) {
            off[idx] = run;
            cur[idx] = run;
            if (which) g_invdeg[idx] = 1.0f / fmaxf((float)c[i], 1.0f);
            cnt[idx] = 0;                    // re-zero for next call
            run += c[i];
        }
    }
    if (tid == 1023) off[N_NODES] = run;
}

// Per edge: place into src-sorted slot p, record its dst-sorted slot q,
// compute edge hidden h = relu(ea @ nn1_w^T + nn1_b) directly into g_hs[p].
__global__ void k_scatter(const int* __restrict__ ei, const float* __restrict__ ea,
                          const float* __restrict__ n1w, const float* __restrict__ n1b) {
    int e = blockIdx.x * blockDim.x + threadIdx.x;
    if (e >= N_EDGES) return;
    int s = ei[e], d = ei[N_EDGES + e];
    int p = atomicAdd(&g_src_cur[s], 1);
    int q = atomicAdd(&g_dst_cur[d], 1);
    g_qs[p] = q;
    float4 a = __ldg((const float4*)&ea[e * 4]);
    float* hd = &g_hs[p * DIM];
#pragma unroll
    for (int j = 0; j < 16; j += 4) {
        float4 h;
        h.x = fmaxf(n1b[j + 0] + a.x * n1w[(j + 0) * 4] + a.y * n1w[(j + 0) * 4 + 1] +
                    a.z * n1w[(j + 0) * 4 + 2] + a.w * n1w[(j + 0) * 4 + 3], 0.0f);
        h.y = fmaxf(n1b[j + 1] + a.x * n1w[(j + 1) * 4] + a.y * n1w[(j + 1) * 4 + 1] +
                    a.z * n1w[(j + 1) * 4 + 2] + a.w * n1w[(j + 1) * 4 + 3], 0.0f);
        h.z = fmaxf(n1b[j + 2] + a.x * n1w[(j + 2) * 4] + a.y * n1w[(j + 2) * 4 + 1] +
                    a.z * n1w[(j + 2) * 4 + 2] + a.w * n1w[(j + 2) * 4 + 3], 0.0f);
        h.w = fmaxf(n1b[j + 3] + a.x * n1w[(j + 3) * 4] + a.y * n1w[(j + 3) * 4 + 1] +
                    a.z * n1w[(j + 3) * 4 + 2] + a.w * n1w[(j + 3) * 4 + 3], 0.0f);
        *(float4*)&hd[j] = h;
    }
}

// ---------------- fused per-round kernel -----------------------------------
// 128 threads = 32 nodes x 4 lanes (R3's proven 4-lane core).
// Phase 1 (r>0): msg-mean (float4 loads) + root + ReLU + GRU, warp-local
// syncs only; updates s_out and g_out.
// Phase 2: P as 32 packed f32x2 regs per lane.
// Phase 3: R3's edge loop verbatim (direct loads, float4 store to dst slot).
__global__ void __launch_bounds__(128) k_round(
    const float* __restrict__ w2, const float* __restrict__ b2,
    const float* __restrict__ cr, const float* __restrict__ cb,
    const float* __restrict__ wih, const float* __restrict__ whh,
    const float* __restrict__ bih, const float* __restrict__ bhh,
    const float* __restrict__ msg_r, float* __restrict__ msg_w, int r) {
    __shared__ ull s_w2p[16 * 8 * 16];   // [d][jj][k], j-pairs packed, 16KB
    __shared__ float s_b2[256];          // [d][k]
    __shared__ float s_cr[256];          // [d][k]
    __shared__ float s_wih[768];         // transposed [d][gate]
    __shared__ float s_whh[768];
    __shared__ float s_out[32][17];
    __shared__ float s_m[32][17];
    int tid = threadIdx.x;
    for (int i = tid; i < 4096; i += 128) {
        int d = i >> 8, k = (i >> 4) & 15, j = i & 15;
        ((float*)&s_w2p[(d * 8 + (j >> 1)) * 16 + k])[j & 1] = w2[i];
    }
    for (int i = tid; i < 256; i += 128) { s_b2[i] = b2[i]; s_cr[i] = cr[i]; }
    for (int i = tid; i < 768; i += 128) {
        int rr = i >> 4, d = i & 15;
        s_wih[d * 48 + rr] = wih[i];
        s_whh[d * 48 + rr] = whh[i];
    }
    int nb = blockIdx.x * 32;
    for (int i = tid; i < 32 * DIM; i += 128) s_out[i >> 4][i & 15] = g_out[nb * DIM + i];
    __syncthreads();

    int l = tid & 3;                     // k-quad index
    int g = tid >> 2;                    // node within block
    int n = nb + g;

    if (r > 0) {
        // ---- fused update: mean(prev msgs) + root + ReLU + GRU ----
        int beg = g_dst_off[n], end = g_dst_off[n + 1];
        float4 a = make_float4(0.f, 0.f, 0.f, 0.f);
        float4 b = make_float4(0.f, 0.f, 0.f, 0.f);
        int q = beg;
        for (; q + 1 < end; q += 2) {
            float4 v0 = __ldg((const float4*)&msg_r[q * DIM + l * 4]);
            float4 v1 = __ldg((const float4*)&msg_r[(q + 1) * DIM + l * 4]);
            a.x += v0.x; a.y += v0.y; a.z += v0.z; a.w += v0.w;
            b.x += v1.x; b.y += v1.y; b.z += v1.z; b.w += v1.w;
        }
        if (q < end) {
            float4 v0 = __ldg((const float4*)&msg_r[q * DIM + l * 4]);
            a.x += v0.x; a.y += v0.y; a.z += v0.z; a.w += v0.w;
        }
        float id = g_invdeg[n];
        float sum4[4] = {a.x + b.x, a.y + b.y, a.z + b.z, a.w + b.w};
        float mloc[4];
#pragma unroll
        for (int kk = 0; kk < 4; ++kk) {
            int k = l * 4 + kk;
            float acc = sum4[kk] * id + cb[k];
#pragma unroll
            for (int d = 0; d < DIM; ++d) acc += s_out[g][d] * s_cr[d * 16 + k];
            mloc[kk] = fmaxf(acc, 0.0f);
        }
        __syncwarp();
#pragma unroll
        for (int kk = 0; kk < 4; ++kk) s_m[g][l * 4 + kk] = mloc[kk];
        __syncwarp();
        float hnew[4];
#pragma unroll
        for (int kk = 0; kk < 4; ++kk) {
            int k = l * 4 + kk;
            float gr = bih[k], gz = bih[k + 16], gn = bih[k + 32];
            float hr = bhh[k], hz = bhh[k + 16], hn = bhh[k + 32];
#pragma unroll
            for (int d = 0; d < DIM; ++d) {
                float md = s_m[g][d], hd = s_out[g][d];
                gr += md * s_wih[d * 48 + k];
                gz += md * s_wih[d * 48 + k + 16];
                gn += md * s_wih[d * 48 + k + 32];
                hr += hd * s_whh[d * 48 + k];
                hz += hd * s_whh[d * 48 + k + 16];
                hn += hd * s_whh[d * 48 + k + 32];
            }
            float rr = 1.0f / (1.0f + expf(-(gr + hr)));
            float zz = 1.0f / (1.0f + expf(-(gz + hz)));
            float nh = tanhf(gn + rr * hn);
            hnew[kk] = (1.0f - zz) * nh + zz * s_out[g][k];
        }
        __syncwarp();                    // all reads of s_out[g] complete
#pragma unroll
        for (int kk = 0; kk < 4; ++kk) {
            s_out[g][l * 4 + kk] = hnew[kk];
            g_out[n * DIM + l * 4 + kk] = hnew[kk];
        }
        __syncwarp();
    }

    // ---- P-compute: P[k][j-pairs] as 32 packed f32x2 regs ----
    ull p2[32];                          // [kk][jj]
    float xb[4];
#pragma unroll
    for (int i = 0; i < 32; ++i) p2[i] = 0ull;
#pragma unroll
    for (int kk = 0; kk < 4; ++kk) xb[kk] = 0.0f;
#pragma unroll
    for (int d = 0; d < 16; ++d) {
        float od = s_out[g][d];
        ull od2;
        asm("mov.b64 %0,{%1,%1};" : "=l"(od2) : "f"(od));
#pragma unroll
        for (int kk = 0; kk < 4; ++kk) {
            int k = l * 4 + kk;
            xb[kk] += od * s_b2[d * 16 + k];
#pragma unroll
            for (int jj = 0; jj < 8; ++jj) {
                ull w = s_w2p[(d * 8 + jj) * 16 + k];
                asm("fma.rn.f32x2 %0,%1,%2,%0;" : "+l"(p2[kk * 8 + jj]) : "l"(od2), "l"(w));
            }
        }
    }

    // ---- edge mainloop (R3 verbatim) ----
    int beg = g_src_off[n], end = g_src_off[n + 1];
    const ulonglong2* hsp = (const ulonglong2*)g_hs;
    for (int i = beg; i < end; ++i) {
        int q = __ldg(&g_qs[i]);
        ulonglong2 A = hsp[i * 4 + 0], B = hsp[i * 4 + 1];
        ulonglong2 C = hsp[i * 4 + 2], D = hsp[i * 4 + 3];
        float4 m4;
        float* mm = (float*)&m4;
#pragma unroll
        for (int kk = 0; kk < 4; ++kk) {
            ull acc;
            asm("mul.rn.f32x2 %0,%1,%2;" : "=l"(acc) : "l"(A.x), "l"(p2[kk * 8 + 0]));
            asm("fma.rn.f32x2 %0,%1,%2,%0;" : "+l"(acc) : "l"(A.y), "l"(p2[kk * 8 + 1]));
            asm("fma.rn.f32x2 %0,%1,%2,%0;" : "+l"(acc) : "l"(B.x), "l"(p2[kk * 8 + 2]));
            asm("fma.rn.f32x2 %0,%1,%2,%0;" : "+l"(acc) : "l"(B.y), "l"(p2[kk * 8 + 3]));
            asm("fma.rn.f32x2 %0,%1,%2,%0;" : "+l"(acc) : "l"(C.x), "l"(p2[kk * 8 + 4]));
            asm("fma.rn.f32x2 %0,%1,%2,%0;" : "+l"(acc) : "l"(C.y), "l"(p2[kk * 8 + 5]));
            asm("fma.rn.f32x2 %0,%1,%2,%0;" : "+l"(acc) : "l"(D.x), "l"(p2[kk * 8 + 6]));
            asm("fma.rn.f32x2 %0,%1,%2,%0;" : "+l"(acc) : "l"(D.y), "l"(p2[kk * 8 + 7]));
            float lo, hi;
            asm("mov.b64 {%0,%1},%2;" : "=f"(lo), "=f"(hi) : "l"(acc));
            mm[kk] = lo + hi + xb[kk];
        }
        ((float4*)msg_w)[q * 4 + l] = m4;    // 64B per edge
    }
}

// ---------------- final update -> d_out ----------------
__global__ void k_fin(const float* __restrict__ msg_r,
                      const float* __restrict__ cr, const float* __restrict__ cb,
                      const float* __restrict__ wih, const float* __restrict__ whh,
                      const float* __restrict__ bih, const float* __restrict__ bhh,
                      float* __restrict__ outw) {
    __shared__ float s_cr[DIM * DIM];
    __shared__ float s_wih[DIM * 3 * DIM];   // transposed [d][gate]
    __shared__ float s_whh[DIM * 3 * DIM];
    __shared__ float s_out[16][DIM];
    __shared__ float s_m[16][DIM];
    int tid = threadIdx.x;
    for (int i = tid; i < DIM * DIM; i += 256) s_cr[i] = cr[i];
    for (int i = tid; i < 3 * DIM * DIM; i += 256) {
        int r = i >> 4, d = i & 15;
        s_wih[d * 48 + r] = wih[i];
        s_whh[d * 48 + r] = whh[i];
    }
    int ln = tid >> 4, k = tid & 15;
    int n = blockIdx.x * 16 + ln;
    float hprev = g_out[n * DIM + k];
    s_out[ln][k] = hprev;
    __syncthreads();

    int beg = g_dst_off[n], end = g_dst_off[n + 1];
    float a0 = 0.0f, a1 = 0.0f, a2 = 0.0f, a3 = 0.0f;
    int q = beg;
    for (; q + 3 < end; q += 4) {
        a0 += __ldg(&msg_r[(q + 0) * DIM + k]);
        a1 += __ldg(&msg_r[(q + 1) * DIM + k]);
        a2 += __ldg(&msg_r[(q + 2) * DIM + k]);
        a3 += __ldg(&msg_r[(q + 3) * DIM + k]);
    }
    for (; q < end; ++q) a0 += __ldg(&msg_r[q * DIM + k]);
    float acc = ((a0 + a1) + (a2 + a3)) * g_invdeg[n] + cb[k];
#pragma unroll
    for (int d = 0; d < DIM; ++d) acc += s_out[ln][d] * s_cr[d * DIM + k];
    float m = fmaxf(acc, 0.0f);
    s_m[ln][k] = m;
    __syncthreads();

    float gr = bih[k], gz = bih[k + 16], gn = bih[k + 32];
    float hr = bhh[k], hz = bhh[k + 16], hn = bhh[k + 32];
#pragma unroll
    for (int d = 0; d < DIM; ++d) {
        float md = s_m[ln][d], hd = s_out[ln][d];
        gr += md * s_wih[d * 48 + k];
        gz += md * s_wih[d * 48 + k + 16];
        gn += md * s_wih[d * 48 + k + 32];
        hr += hd * s_whh[d * 48 + k];
        hz += hd * s_whh[d * 48 + k + 16];
        hn += hd * s_whh[d * 48 + k + 32];
    }
    float r = 1.0f / (1.0f + expf(-(gr + hr)));
    float z = 1.0f / (1.0f + expf(-(gz + hz)));
    float nh = tanhf(gn + r * hn);
    outw[n * DIM + k] = (1.0f - z) * nh + z * hprev;
}

// ---------------- host launcher ----------------
extern "C" void kernel_launch(void* const* d_in, const int* in_sizes, int n_in,
                              void* d_out, int out_size) {
    const float* x         = (const float*)d_in[0];
    const int*   ei        = (const int*)  d_in[1];
    const float* ea        = (const float*)d_in[2];
    const float* lin0_w    = (const float*)d_in[3];
    const float* lin0_b    = (const float*)d_in[4];
    const float* nn1_w     = (const float*)d_in[5];
    const float* nn1_b     = (const float*)d_in[6];
    const float* nn2_w     = (const float*)d_in[7];
    const float* nn2_b     = (const float*)d_in[8];
    const float* conv_root = (const float*)d_in[9];
    const float* conv_bias = (const float*)d_in[10];
    const float* w_ih      = (const float*)d_in[11];
    const float* w_hh      = (const float*)d_in[12];
    const float* b_ih      = (const float*)d_in[13];
    const float* b_hh      = (const float*)d_in[14];

    float *m0 = nullptr, *m1 = nullptr;
    cudaGetSymbolAddress((void**)&m0, g_msg0);
    cudaGetSymbolAddress((void**)&m1, g_msg1);

    k_hist<<<N_EDGES / 256 + (N_NODES * DIM) / 256, 256>>>(x, ei, lin0_w, lin0_b);
    k_scan<<<2, 1024>>>();
    k_scatter<<<(N_EDGES + 255) / 256, 256>>>(ei, ea, nn1_w, nn1_b);

    // k_round r: (r>0) update with round r-1 msgs, then emit round r msgs.
    // r writes m[r&1]; k_fin consumes round-5 msgs (m1) -> d_out.
    for (int r = 0; r < 6; ++r) {
        const float* mr = ((r - 1) & 1) ? m1 : m0;
        float* mw = (r & 1) ? m1 : m0;
        k_round<<<N_NODES / 32, 128>>>(nn2_w, nn2_b, conv_root, conv_bias,
                                       w_ih, w_hh, b_ih, b_hh, mr, mw, r);
    }
    k_fin<<<N_NODES / 16, 256>>>(m1, conv_root, conv_bias, w_ih, w_hh,
                                 b_ih, b_hh, (float*)d_out);
}